// round 12
// baseline (speedup 1.0000x reference)
#include <cuda_runtime.h>
#include <cuda_bf16.h>
#include <cstdint>

#define N_NODES_MAX 50000
#define D_FEAT 128
#define H1 128
#define H2 64

// Scratch: per-node precomputed attention contributions (bias folded into A1).
__device__ float g_A1[N_NODES_MAX * H2];
__device__ float g_A2[N_NODES_MAX * H2];
__device__ int   g_edges_are_i64;   // 1 if edge buffer is int64, 0 if int32

// ---------------- smem layout (bytes) ----------------
// Tiles are bf16 with row stride 136 halves (272 B): for a quad reading
// (gid, tig) -> addr = gid*272 + tig*4, bank = (68*gid + tig) % 32 =
// (4*gid + tig) % 32: all 32 lanes distinct -> conflict-free.
#define TM 128
#define KSB 272                       // bytes per tile row (136 halves)
#define SM_AHI 0
#define SM_ALO (SM_AHI + TM * KSB)    // 34816
#define SM_BHI (SM_ALO + TM * KSB)
#define SM_BLO (SM_BHI + TM * KSB)
#define NODE_SMEM_BYTES (SM_BLO + TM * KSB)   // 139264
#define NODE_THREADS 256

__device__ __forceinline__ uint32_t pack_bf16(float a, float b) {
    __nv_bfloat162 t = __floats2bfloat162_rn(a, b);
    return *reinterpret_cast<uint32_t*>(&t);
}
// Split x into hi (bf16) and lo (bf16 of the residual); returns packed pairs.
__device__ __forceinline__ void split_pair(float x0, float x1,
                                           uint32_t& hi, uint32_t& lo) {
    __nv_bfloat16 h0 = __float2bfloat16_rn(x0);
    __nv_bfloat16 h1 = __float2bfloat16_rn(x1);
    hi = pack_bf16(x0, x1);   // __floats2bfloat162_rn == per-element rn
    lo = pack_bf16(x0 - __bfloat162float(h0), x1 - __bfloat162float(h1));
}

__device__ __forceinline__ void mma_bf16(float* d, const uint32_t* a, const uint32_t* b) {
    asm volatile(
        "mma.sync.aligned.m16n8k16.row.col.f32.bf16.bf16.f32 "
        "{%0,%1,%2,%3}, {%4,%5,%6,%7}, {%8,%9}, {%0,%1,%2,%3};\n"
        : "+f"(d[0]), "+f"(d[1]), "+f"(d[2]), "+f"(d[3])
        : "r"(a[0]), "r"(a[1]), "r"(a[2]), "r"(a[3]), "r"(b[0]), "r"(b[1]));
}

// ---------------- Node precompute kernel ----------------
// gridDim.x = ceil(nNodes/128), gridDim.y = 2 (path 0 = nb/A1, path 1 = self/A2)
// 256 threads = 8 warps, warp grid 2(m) x 4(n).
// Phase 1: H[128][128] = relu(F @ W + b)       warp tile 64x32 (mf=4, nf=4)
// Phase 2: A[128][64]  = H @ Wa (+ b_att1)     warp tile 64x16 (mf=4, nf=2)
// Double-bf16 (hi/lo) emulation: 3 MMA products per tile step, fp32 accum.
extern "C" __global__ void __launch_bounds__(NODE_THREADS, 1)
node_precompute_kernel(const float* __restrict__ features,
                       const int*   __restrict__ edges_words,
                       const float* __restrict__ W_nb,
                       const float* __restrict__ b_nb,
                       const float* __restrict__ W_self,
                       const float* __restrict__ b_self,
                       const float* __restrict__ W_att1,
                       const float* __restrict__ b_att1,
                       int nNodes)
{
    extern __shared__ char smem[];

    const int tid  = threadIdx.x;
    const int path = blockIdx.y;
    const int node0 = blockIdx.x * TM;
    const int valid = min(TM, nNodes - node0);

    // ---- Edge dtype detection (block (0,0) only; block-uniform branch) ----
    if (blockIdx.x == 0 && path == 0) {
        int nz = 0;
        for (int i = tid; i < 2048; i += NODE_THREADS) nz |= edges_words[2 * i + 1];
        int any = __syncthreads_or(nz);
        if (tid == 0) g_edges_are_i64 = (any == 0) ? 1 : 0;
    }

    const float* W   = (path == 0) ? W_nb : W_self;
    const float* bW  = (path == 0) ? b_nb : b_self;
    const float* WaG = W_att1 + (size_t)path * H1 * H2;   // rows [path*128, +128) of [256][64]
    float* Aout = (path == 0) ? g_A1 : g_A2;

    // ---- Stage F -> Ahi/Alo  ([row][k] bf16, stride 272B) ----
    for (int idx = tid; idx < TM * 32; idx += NODE_THREADS) {
        int row = idx >> 5, c4 = idx & 31;
        float4 v = make_float4(0.f, 0.f, 0.f, 0.f);
        if (row < valid)
            v = *reinterpret_cast<const float4*>(&features[(size_t)(node0 + row) * D_FEAT + c4 * 4]);
        const int o = row * KSB + c4 * 8;
        uint32_t h0, l0, h1, l1;
        split_pair(v.x, v.y, h0, l0);
        split_pair(v.z, v.w, h1, l1);
        *reinterpret_cast<uint32_t*>(smem + SM_AHI + o)     = h0;
        *reinterpret_cast<uint32_t*>(smem + SM_AHI + o + 4) = h1;
        *reinterpret_cast<uint32_t*>(smem + SM_ALO + o)     = l0;
        *reinterpret_cast<uint32_t*>(smem + SM_ALO + o + 4) = l1;
    }
    // ---- Stage W^T -> Bhi/Blo  ([n][k] bf16): Bt[n][k] = W[k][n] ----
    for (int idx = tid; idx < H1 * H1; idx += NODE_THREADS) {
        int k = idx >> 7, n = idx & 127;
        float x = W[(size_t)k * H1 + n];
        __nv_bfloat16 h = __float2bfloat16_rn(x);
        const int o = n * KSB + k * 2;
        *reinterpret_cast<__nv_bfloat16*>(smem + SM_BHI + o) = h;
        *reinterpret_cast<__nv_bfloat16*>(smem + SM_BLO + o) =
            __float2bfloat16_rn(x - __bfloat162float(h));
    }
    __syncthreads();

    const int lane = tid & 31;
    const int wid  = tid >> 5;
    const int gid  = lane >> 2;        // 0..7
    const int tig  = lane & 3;         // 0..3
    const int wm   = wid >> 2;         // 0..1
    const int wn   = wid & 3;          // 0..3

    // ================= Phase 1: H = relu(F @ W + b) =================
    float acc[4][4][4];
    #pragma unroll
    for (int mf = 0; mf < 4; mf++)
        #pragma unroll
        for (int nf = 0; nf < 4; nf++)
            #pragma unroll
            for (int r = 0; r < 4; r++) acc[mf][nf][r] = 0.f;

    for (int kb = 0; kb < D_FEAT / 16; kb++) {
        const int kbyte = kb * 32 + tig * 4;
        uint32_t ahi[4][4], alo[4][4];
        #pragma unroll
        for (int mf = 0; mf < 4; mf++) {
            const int rb = (wm * 64 + mf * 16 + gid) * KSB + kbyte;
            ahi[mf][0] = *reinterpret_cast<uint32_t*>(smem + SM_AHI + rb);
            ahi[mf][1] = *reinterpret_cast<uint32_t*>(smem + SM_AHI + rb + 8 * KSB);
            ahi[mf][2] = *reinterpret_cast<uint32_t*>(smem + SM_AHI + rb + 16);
            ahi[mf][3] = *reinterpret_cast<uint32_t*>(smem + SM_AHI + rb + 8 * KSB + 16);
            alo[mf][0] = *reinterpret_cast<uint32_t*>(smem + SM_ALO + rb);
            alo[mf][1] = *reinterpret_cast<uint32_t*>(smem + SM_ALO + rb + 8 * KSB);
            alo[mf][2] = *reinterpret_cast<uint32_t*>(smem + SM_ALO + rb + 16);
            alo[mf][3] = *reinterpret_cast<uint32_t*>(smem + SM_ALO + rb + 8 * KSB + 16);
        }
        uint32_t bhi[4][2], blo[4][2];
        #pragma unroll
        for (int nf = 0; nf < 4; nf++) {
            const int nb = (wn * 32 + nf * 8 + gid) * KSB + kbyte;
            bhi[nf][0] = *reinterpret_cast<uint32_t*>(smem + SM_BHI + nb);
            bhi[nf][1] = *reinterpret_cast<uint32_t*>(smem + SM_BHI + nb + 16);
            blo[nf][0] = *reinterpret_cast<uint32_t*>(smem + SM_BLO + nb);
            blo[nf][1] = *reinterpret_cast<uint32_t*>(smem + SM_BLO + nb + 16);
        }
        #pragma unroll
        for (int mf = 0; mf < 4; mf++)
            #pragma unroll
            for (int nf = 0; nf < 4; nf++) {
                mma_bf16(acc[mf][nf], ahi[mf], bhi[nf]);
                mma_bf16(acc[mf][nf], ahi[mf], blo[nf]);
                mma_bf16(acc[mf][nf], alo[mf], bhi[nf]);
            }
    }

    // bias + relu, re-split H into Ahi/Alo (barrier first: tiles still being read)
    float bias0[4], bias1[4];
    #pragma unroll
    for (int nf = 0; nf < 4; nf++) {
        int c = wn * 32 + nf * 8 + 2 * tig;
        bias0[nf] = __ldg(&bW[c]);
        bias1[nf] = __ldg(&bW[c + 1]);
    }
    __syncthreads();

    #pragma unroll
    for (int mf = 0; mf < 4; mf++) {
        int r0 = wm * 64 + mf * 16 + gid;
        #pragma unroll
        for (int nf = 0; nf < 4; nf++) {
            int c = wn * 32 + nf * 8 + 2 * tig;
            float x0 = fmaxf(acc[mf][nf][0] + bias0[nf], 0.f);
            float x1 = fmaxf(acc[mf][nf][1] + bias1[nf], 0.f);
            float x2 = fmaxf(acc[mf][nf][2] + bias0[nf], 0.f);
            float x3 = fmaxf(acc[mf][nf][3] + bias1[nf], 0.f);
            uint32_t h, l;
            split_pair(x0, x1, h, l);
            *reinterpret_cast<uint32_t*>(smem + SM_AHI + r0 * KSB + c * 2) = h;
            *reinterpret_cast<uint32_t*>(smem + SM_ALO + r0 * KSB + c * 2) = l;
            split_pair(x2, x3, h, l);
            *reinterpret_cast<uint32_t*>(smem + SM_AHI + (r0 + 8) * KSB + c * 2) = h;
            *reinterpret_cast<uint32_t*>(smem + SM_ALO + (r0 + 8) * KSB + c * 2) = l;
        }
    }
    // ---- Stage Wa^T -> Bhi/Blo ([n][k], n<64): Bt[n][k] = Wa[k][n] ----
    for (int idx = tid; idx < H1 * H2; idx += NODE_THREADS) {
        int k = idx >> 6, n = idx & 63;
        float x = WaG[(size_t)k * H2 + n];
        __nv_bfloat16 h = __float2bfloat16_rn(x);
        const int o = n * KSB + k * 2;
        *reinterpret_cast<__nv_bfloat16*>(smem + SM_BHI + o) = h;
        *reinterpret_cast<__nv_bfloat16*>(smem + SM_BLO + o) =
            __float2bfloat16_rn(x - __bfloat162float(h));
    }
    __syncthreads();

    // ================= Phase 2: A = H @ Wa (+ b_att1 path 0) =================
    float acc2[4][2][4];
    #pragma unroll
    for (int mf = 0; mf < 4; mf++)
        #pragma unroll
        for (int nf = 0; nf < 2; nf++)
            #pragma unroll
            for (int r = 0; r < 4; r++) acc2[mf][nf][r] = 0.f;

    for (int kb = 0; kb < H1 / 16; kb++) {
        const int kbyte = kb * 32 + tig * 4;
        uint32_t ahi[4][4], alo[4][4];
        #pragma unroll
        for (int mf = 0; mf < 4; mf++) {
            const int rb = (wm * 64 + mf * 16 + gid) * KSB + kbyte;
            ahi[mf][0] = *reinterpret_cast<uint32_t*>(smem + SM_AHI + rb);
            ahi[mf][1] = *reinterpret_cast<uint32_t*>(smem + SM_AHI + rb + 8 * KSB);
            ahi[mf][2] = *reinterpret_cast<uint32_t*>(smem + SM_AHI + rb + 16);
            ahi[mf][3] = *reinterpret_cast<uint32_t*>(smem + SM_AHI + rb + 8 * KSB + 16);
            alo[mf][0] = *reinterpret_cast<uint32_t*>(smem + SM_ALO + rb);
            alo[mf][1] = *reinterpret_cast<uint32_t*>(smem + SM_ALO + rb + 8 * KSB);
            alo[mf][2] = *reinterpret_cast<uint32_t*>(smem + SM_ALO + rb + 16);
            alo[mf][3] = *reinterpret_cast<uint32_t*>(smem + SM_ALO + rb + 8 * KSB + 16);
        }
        uint32_t bhi[2][2], blo[2][2];
        #pragma unroll
        for (int nf = 0; nf < 2; nf++) {
            const int nb = (wn * 16 + nf * 8 + gid) * KSB + kbyte;
            bhi[nf][0] = *reinterpret_cast<uint32_t*>(smem + SM_BHI + nb);
            bhi[nf][1] = *reinterpret_cast<uint32_t*>(smem + SM_BHI + nb + 16);
            blo[nf][0] = *reinterpret_cast<uint32_t*>(smem + SM_BLO + nb);
            blo[nf][1] = *reinterpret_cast<uint32_t*>(smem + SM_BLO + nb + 16);
        }
        #pragma unroll
        for (int mf = 0; mf < 4; mf++)
            #pragma unroll
            for (int nf = 0; nf < 2; nf++) {
                mma_bf16(acc2[mf][nf], ahi[mf], bhi[nf]);
                mma_bf16(acc2[mf][nf], ahi[mf], blo[nf]);
                mma_bf16(acc2[mf][nf], alo[mf], bhi[nf]);
            }
    }

    float ba0[2] = {0.f, 0.f}, ba1[2] = {0.f, 0.f};
    if (path == 0) {
        #pragma unroll
        for (int nf = 0; nf < 2; nf++) {
            int c = wn * 16 + nf * 8 + 2 * tig;
            ba0[nf] = __ldg(&b_att1[c]);
            ba1[nf] = __ldg(&b_att1[c + 1]);
        }
    }

    #pragma unroll
    for (int mf = 0; mf < 4; mf++) {
        int r0 = wm * 64 + mf * 16 + gid;
        #pragma unroll
        for (int nf = 0; nf < 2; nf++) {
            int c = wn * 16 + nf * 8 + 2 * tig;
            if (r0 < valid) {
                float2 v;
                v.x = acc2[mf][nf][0] + ba0[nf];
                v.y = acc2[mf][nf][1] + ba1[nf];
                *reinterpret_cast<float2*>(&Aout[(size_t)(node0 + r0) * H2 + c]) = v;
            }
            if (r0 + 8 < valid) {
                float2 v;
                v.x = acc2[mf][nf][2] + ba0[nf];
                v.y = acc2[mf][nf][3] + ba1[nf];
                *reinterpret_cast<float2*>(&Aout[(size_t)(node0 + r0 + 8) * H2 + c]) = v;
            }
        }
    }
}

// ---------------- Edge kernel ----------------
// 4 edges per warp, 8 lanes per edge, float4 gathers.
// out[e] = relu(A1[n1] + A2[n2]) . W_att2 + b_att2
extern "C" __global__ void __launch_bounds__(256)
edge_kernel(const void* __restrict__ edges_raw,
            const float* __restrict__ W_att2,
            const float* __restrict__ b_att2,
            float* __restrict__ out,
            int nEdges)
{
    const int warp = (blockIdx.x * blockDim.x + threadIdx.x) >> 5;
    const int lane = threadIdx.x & 31;
    const int sub  = lane >> 3;        // edge slot within warp (0..3)
    const int c    = lane & 7;         // 8-float chunk within edge (0..7)

    const long long e = (long long)warp * 4 + sub;
    if (e >= nEdges) return;           // group-uniform exit

    int n1, n2;
    if (g_edges_are_i64) {
        const longlong2 ed =
            *reinterpret_cast<const longlong2*>((const char*)edges_raw + 16 * e);
        n1 = (int)ed.x;
        n2 = (int)ed.y;
    } else {
        const int2 ed =
            *reinterpret_cast<const int2*>((const char*)edges_raw + 8 * e);
        n1 = ed.x;
        n2 = ed.y;
    }

    const float4* pa = reinterpret_cast<const float4*>(&g_A1[(size_t)n1 * H2 + c * 8]);
    const float4* pb = reinterpret_cast<const float4*>(&g_A2[(size_t)n2 * H2 + c * 8]);
    const float4 a0 = pa[0], a1 = pa[1];
    const float4 b0 = pb[0], b1 = pb[1];
    const float4 w0 = __ldg(reinterpret_cast<const float4*>(&W_att2[c * 8]));
    const float4 w1 = __ldg(reinterpret_cast<const float4*>(&W_att2[c * 8 + 4]));

    float s;
    s  = fmaxf(a0.x + b0.x, 0.f) * w0.x;
    s  = fmaf(fmaxf(a0.y + b0.y, 0.f), w0.y, s);
    s  = fmaf(fmaxf(a0.z + b0.z, 0.f), w0.z, s);
    s  = fmaf(fmaxf(a0.w + b0.w, 0.f), w0.w, s);
    s  = fmaf(fmaxf(a1.x + b1.x, 0.f), w1.x, s);
    s  = fmaf(fmaxf(a1.y + b1.y, 0.f), w1.y, s);
    s  = fmaf(fmaxf(a1.z + b1.z, 0.f), w1.z, s);
    s  = fmaf(fmaxf(a1.w + b1.w, 0.f), w1.w, s);

    const unsigned gmask = 0xFFu << (sub * 8);
    s += __shfl_xor_sync(gmask, s, 1);
    s += __shfl_xor_sync(gmask, s, 2);
    s += __shfl_xor_sync(gmask, s, 4);

    if (c == 0) out[e] = s + __ldg(&b_att2[0]);
}

// ---------------- Launch ----------------
extern "C" void kernel_launch(void* const* d_in, const int* in_sizes, int n_in,
                              void* d_out, int out_size)
{
    const float* features = (const float*)d_in[0];
    const void*  edges    = d_in[1];
    const float* W_nb     = (const float*)d_in[2];
    const float* b_nb     = (const float*)d_in[3];
    const float* W_self   = (const float*)d_in[4];
    const float* b_self   = (const float*)d_in[5];
    const float* W_att1   = (const float*)d_in[6];
    const float* b_att1   = (const float*)d_in[7];
    const float* W_att2   = (const float*)d_in[8];
    const float* b_att2   = (const float*)d_in[9];
    float* out = (float*)d_out;

    const int nNodes = in_sizes[0] / D_FEAT;
    const int nEdges = in_sizes[1] / 2;

    cudaFuncSetAttribute(node_precompute_kernel,
                         cudaFuncAttributeMaxDynamicSharedMemorySize, NODE_SMEM_BYTES);

    dim3 gridN((nNodes + TM - 1) / TM, 2);
    node_precompute_kernel<<<gridN, NODE_THREADS, NODE_SMEM_BYTES>>>(
        features, (const int*)edges, W_nb, b_nb, W_self, b_self, W_att1, b_att1, nNodes);

    const int edgesPerBlock = (256 / 32) * 4;   // 8 warps x 4 edges
    int gridE = (nEdges + edgesPerBlock - 1) / edgesPerBlock;
    edge_kernel<<<gridE, 256>>>(edges, W_att2, b_att2, out, nEdges);
}